// round 13
// baseline (speedup 1.0000x reference)
#include <cuda_runtime.h>
#include <cuda_fp16.h>
#include <math.h>
#include <stdint.h>

#define DIM      128
#define DIM4     32          // DIM / 4
#define MAXN     100000
#define MAXE     1600000
#define BETA     0.001f
#define ONE_MB   0.999f      // 1 - BETA
#define EPS_NORM 1e-12f

#define SLOTS    64          // per-row edge bin (Poisson(16): P(>64) ~ 1e-20)

#define BK        64                 // K elements per smem pass
#define AS_STRIDE (BK + 8)           // 72 halves = 144B row stride

// ---------------- device scratch (no allocations allowed) ----------------
__device__ __half g_support[(size_t)MAXN * DIM];  // 25.6 MB, keep L2-resident
__device__ __half g_wt[DIM * DIM];                // W^T, [n][k] fp16
__device__ int    g_count[MAXN];
__device__ int2   g_slot [(size_t)MAXN * SLOTS];  // binned (col, val-bits)

// ---------------- PTX helpers ---------------------------------------------
__device__ __forceinline__ uint32_t smem_u32(const void* p) {
    return (uint32_t)__cvta_generic_to_shared(p);
}
__device__ __forceinline__ void ldm_x4(uint32_t& r0, uint32_t& r1,
                                       uint32_t& r2, uint32_t& r3, uint32_t addr) {
    asm volatile("ldmatrix.sync.aligned.m8n8.x4.shared.b16 {%0,%1,%2,%3}, [%4];"
        : "=r"(r0), "=r"(r1), "=r"(r2), "=r"(r3) : "r"(addr));
}
__device__ __forceinline__ void mma16816(float* c, const uint32_t* a, const uint32_t* b) {
    asm volatile("mma.sync.aligned.m16n8k16.row.col.f32.f16.f16.f32 "
        "{%0,%1,%2,%3}, {%4,%5,%6,%7}, {%8,%9}, {%0,%1,%2,%3};"
        : "+f"(c[0]), "+f"(c[1]), "+f"(c[2]), "+f"(c[3])
        : "r"(a[0]), "r"(a[1]), "r"(a[2]), "r"(a[3]), "r"(b[0]), "r"(b[1]));
}

// ---- packed fp32 (f32x2) helpers: FFMA2 is PTX-only on sm_103a -----------
__device__ __forceinline__ unsigned long long pk2(float x, float y) {
    unsigned long long r;
    asm("mov.b64 %0, {%1, %2};" : "=l"(r) : "f"(x), "f"(y));
    return r;
}
__device__ __forceinline__ void upk2(float& x, float& y, unsigned long long v) {
    asm("mov.b64 {%0, %1}, %2;" : "=f"(x), "=f"(y) : "l"(v));
}
__device__ __forceinline__ unsigned long long f2fma(
    unsigned long long a, unsigned long long b, unsigned long long c) {
    unsigned long long d;
    asm("fma.rn.f32x2 %0, %1, %2, %3;" : "=l"(d) : "l"(a), "l"(b), "l"(c));
    return d;
}
__device__ __forceinline__ unsigned long long h2f2(uint32_t h) {
    float2 f = __half22float2(*(__half2*)&h);
    return pk2(f.x, f.y);
}

// ---------------- 0b. W [k][n] fp32 -> g_wt [n][k] fp16 -------------------
__global__ void wt_kernel(const float* __restrict__ W) {
    int tid = blockIdx.x * blockDim.x + threadIdx.x;
    if (tid < DIM * DIM) {
        int n = tid >> 7, k = tid & 127;
        g_wt[n * DIM + k] = __float2half_rn(W[k * DIM + n]);
    }
}

// ---------------- 1. support = input @ W  (HMMA fp16, fp32 accum) --------
__global__ __launch_bounds__(256) void gemm_hmma_kernel(
    const float* __restrict__ A, int M)
{
    __shared__ __half As[128 * AS_STRIDE];   // [m][k_local]
    __shared__ __half Ws[128 * AS_STRIDE];   // [n][k_local]

    const int tid  = threadIdx.x;
    const int warp = tid >> 5;
    const int lane = tid & 31;
    const int m0   = blockIdx.x * 128;

    const int wm = warp & 1;
    const int wn = warp >> 1;
    const int mbase = wm * 64;
    const int nbase = wn * 32;

    float acc[4][4][4];
#pragma unroll
    for (int i = 0; i < 4; i++)
#pragma unroll
        for (int j = 0; j < 4; j++)
#pragma unroll
            for (int q = 0; q < 4; q++) acc[i][j][q] = 0.f;

    const float4* A4 = (const float4*)A;
    const uint32_t as_base = smem_u32(As);
    const uint32_t ws_base = smem_u32(Ws);

    const int mat = lane >> 3;
    const int rin = lane & 7;
    const int rofs = rin + (mat & 1) * 8;
    const int kofs = (mat >> 1) * 8;

    for (int pass = 0; pass < 2; pass++) {
        const int kg = pass * BK;

#pragma unroll
        for (int it = 0; it < 8; it++) {
            int idx4 = tid + it * 256;
            int row  = idx4 >> 4;
            int c4   = idx4 & 15;
            int rg   = m0 + row; if (rg >= M) rg = M - 1;
            float4 f = __ldcs(&A4[(size_t)rg * DIM4 + (kg >> 2) + c4]);  // stream A
            __half2* dst = (__half2*)&As[row * AS_STRIDE + c4 * 4];
            dst[0] = __floats2half2_rn(f.x, f.y);
            dst[1] = __floats2half2_rn(f.z, f.w);
        }
#pragma unroll
        for (int it = 0; it < 4; it++) {
            int idx8 = tid + it * 256;
            int row  = idx8 >> 3;
            int c8   = idx8 & 7;
            uint4 u = *(const uint4*)&g_wt[row * DIM + kg + c8 * 8];
            *(uint4*)&Ws[row * AS_STRIDE + c8 * 8] = u;
        }
        __syncthreads();

#pragma unroll
        for (int ks = 0; ks < BK / 16; ks++) {
            const int k0 = ks * 16;

            uint32_t a[4][4];
#pragma unroll
            for (int mt = 0; mt < 4; mt++) {
                uint32_t addr = as_base +
                    ((mbase + mt * 16 + rofs) * AS_STRIDE + k0 + kofs) * 2;
                ldm_x4(a[mt][0], a[mt][1], a[mt][2], a[mt][3], addr);
            }
            uint32_t b[4][2];
#pragma unroll
            for (int g = 0; g < 2; g++) {
                uint32_t addr = ws_base +
                    ((nbase + g * 16 + rofs) * AS_STRIDE + k0 + kofs) * 2;
                uint32_t r0, r1, r2, r3;
                ldm_x4(r0, r1, r2, r3, addr);
                b[g * 2 + 0][0] = r0; b[g * 2 + 0][1] = r2;
                b[g * 2 + 1][0] = r1; b[g * 2 + 1][1] = r3;
            }
#pragma unroll
            for (int mt = 0; mt < 4; mt++)
#pragma unroll
                for (int nt = 0; nt < 4; nt++)
                    mma16816(acc[mt][nt], a[mt], b[nt]);
        }
        __syncthreads();
    }

    // support stores: default caching (we WANT these resident in L2)
#pragma unroll
    for (int mt = 0; mt < 4; mt++) {
        int m1 = m0 + mbase + mt * 16 + (lane >> 2);
        int m2 = m1 + 8;
#pragma unroll
        for (int nt = 0; nt < 4; nt++) {
            int nc = nbase + nt * 8 + (lane & 3) * 2;
            if (m1 < M)
                *(__half2*)&g_support[(size_t)m1 * DIM + nc] =
                    __floats2half2_rn(acc[mt][nt][0], acc[mt][nt][1]);
            if (m2 < M)
                *(__half2*)&g_support[(size_t)m2 * DIM + nc] =
                    __floats2half2_rn(acc[mt][nt][2], acc[mt][nt][3]);
        }
    }
}

// ---------------- 2. single-pass slot scatter (1 edge/thread: max MLP) -----
__global__ void slot_scatter_kernel(const int* __restrict__ rows,
                                    const int* __restrict__ cols,
                                    const float* __restrict__ vals, int e) {
    int i = blockIdx.x * blockDim.x + threadIdx.x;
    if (i < e) {
        int   r = __ldcs(rows + i);
        int   c = __ldcs(cols + i);
        float v = __ldcs(vals + i);
        int pos = atomicAdd(&g_count[r], 1);
        g_slot[(size_t)r * SLOTS + pos] = make_int2(c, __float_as_int(v));
    }
}

// ---------------- 3. fused gather + blend + L2-normalize + bias ----------
// One warp per row. Edge list read via broadcast L1 loads (no shfl);
// packed f32x2 FMA; byte-offset gather addressing.
__global__ __launch_bounds__(256) void agg_kernel(
    const float* __restrict__ input,
    const float* __restrict__ bias,
    float* __restrict__ out, int n)
{
    const int gtid = blockIdx.x * blockDim.x + threadIdx.x;
    const int row  = gtid >> 5;
    const int lane = gtid & 31;
    if (row >= n) return;

    const int cnt = min(g_count[row], SLOTS);
    const int2* slot = g_slot + (size_t)row * SLOTS;

    // lane-fixed byte base into support; per-edge offset = col * 256B
    const char* supb = (const char*)g_support + lane * 8;

    unsigned long long acc01 = 0ull, acc23 = 0ull;   // packed f32x2 pairs

    int j = 0;
    for (; j + 4 <= cnt; j += 4) {
        // broadcast edge reads (same addr across warp -> 1 wavefront, L1-hot)
        int2 e0 = __ldg(slot + j + 0);
        int2 e1 = __ldg(slot + j + 1);
        int2 e2 = __ldg(slot + j + 2);
        int2 e3 = __ldg(slot + j + 3);
        // 4 independent gathers in flight
        uint2 u0 = *(const uint2*)(supb + ((size_t)(unsigned)e0.x << 8));
        uint2 u1 = *(const uint2*)(supb + ((size_t)(unsigned)e1.x << 8));
        uint2 u2 = *(const uint2*)(supb + ((size_t)(unsigned)e2.x << 8));
        uint2 u3 = *(const uint2*)(supb + ((size_t)(unsigned)e3.x << 8));

        float v0 = __int_as_float(e0.y), v1 = __int_as_float(e1.y);
        float v2 = __int_as_float(e2.y), v3 = __int_as_float(e3.y);
        unsigned long long vv0 = pk2(v0, v0), vv1 = pk2(v1, v1);
        unsigned long long vv2 = pk2(v2, v2), vv3 = pk2(v3, v3);

        acc01 = f2fma(h2f2(u0.x), vv0, acc01);
        acc23 = f2fma(h2f2(u0.y), vv0, acc23);
        acc01 = f2fma(h2f2(u1.x), vv1, acc01);
        acc23 = f2fma(h2f2(u1.y), vv1, acc23);
        acc01 = f2fma(h2f2(u2.x), vv2, acc01);
        acc23 = f2fma(h2f2(u2.y), vv2, acc23);
        acc01 = f2fma(h2f2(u3.x), vv3, acc01);
        acc23 = f2fma(h2f2(u3.y), vv3, acc23);
    }
    for (; j < cnt; j++) {
        int2 ed = __ldg(slot + j);
        uint2 u = *(const uint2*)(supb + ((size_t)(unsigned)ed.x << 8));
        float v = __int_as_float(ed.y);
        unsigned long long vv = pk2(v, v);
        acc01 = f2fma(h2f2(u.x), vv, acc01);
        acc23 = f2fma(h2f2(u.y), vv, acc23);
    }

    float4 acc;
    upk2(acc.x, acc.y, acc01);
    upk2(acc.z, acc.w, acc23);

    float4 in4 = __ldcs(&((const float4*)input)[row * DIM4 + lane]);  // stream
    float4 o;
    o.x = fmaf(BETA, in4.x, ONE_MB * acc.x);
    o.y = fmaf(BETA, in4.y, ONE_MB * acc.y);
    o.z = fmaf(BETA, in4.z, ONE_MB * acc.z);
    o.w = fmaf(BETA, in4.w, ONE_MB * acc.w);

    float ss = o.x * o.x + o.y * o.y + o.z * o.z + o.w * o.w;
#pragma unroll
    for (int off = 16; off; off >>= 1)
        ss += __shfl_xor_sync(0xffffffffu, ss, off);

    float inv = 1.f / fmaxf(sqrtf(ss), EPS_NORM);

    float4 b4 = ((const float4*)bias)[lane];
    o.x = fmaf(o.x, inv, b4.x);
    o.y = fmaf(o.y, inv, b4.y);
    o.z = fmaf(o.z, inv, b4.z);
    o.w = fmaf(o.w, inv, b4.w);

    __stcs(&((float4*)out)[row * DIM4 + lane], o);     // streaming store
}

// ---------------- launch ---------------------------------------------------
extern "C" void kernel_launch(void* const* d_in, const int* in_sizes, int n_in,
                              void* d_out, int out_size) {
    const float* input     = (const float*)d_in[0];
    const int*   edge_rows = (const int*)  d_in[1];
    const int*   edge_cols = (const int*)  d_in[2];
    const float* edge_vals = (const float*)d_in[3];
    const float* weight    = (const float*)d_in[4];
    const float* bias      = (const float*)d_in[5];
    float*       out       = (float*)d_out;

    const int n = in_sizes[0] / DIM;   // 100000
    const int e = in_sizes[1];         // 1600000

    static cudaStream_t s2 = nullptr;
    static cudaEvent_t  ev_fork = nullptr, ev_join = nullptr;
    static int* count_addr = nullptr;
    if (!s2) {
        cudaStreamCreateWithFlags(&s2, cudaStreamNonBlocking);
        cudaEventCreateWithFlags(&ev_fork, cudaEventDisableTiming);
        cudaEventCreateWithFlags(&ev_join, cudaEventDisableTiming);
        cudaGetSymbolAddress((void**)&count_addr, g_count);
    }

    // fork
    cudaEventRecord(ev_fork, 0);
    cudaStreamWaitEvent(s2, ev_fork, 0);

    // branch B (side stream): dense projection
    wt_kernel<<<(DIM * DIM + 255) / 256, 256, 0, s2>>>(weight);
    gemm_hmma_kernel<<<(n + 127) / 128, 256, 0, s2>>>(input, n);
    cudaEventRecord(ev_join, s2);

    // branch A (main stream): zero counters (memset node) + edge binning
    cudaMemsetAsync(count_addr, 0, (size_t)n * sizeof(int), 0);
    slot_scatter_kernel<<<(e + 255) / 256, 256>>>(edge_rows, edge_cols, edge_vals, e);

    // join: agg needs both support (branch B) and bins (branch A)
    cudaStreamWaitEvent(0, ev_join, 0);
    agg_kernel<<<((long long)n * 32 + 255) / 256, 256>>>(input, bias, out, n);
}

// round 14
// speedup vs baseline: 1.1620x; 1.1620x over previous
#include <cuda_runtime.h>
#include <cuda_fp16.h>
#include <math.h>
#include <stdint.h>

#define DIM      128
#define DIM4     32          // DIM / 4
#define MAXN     100000
#define MAXE     1600000
#define BETA     0.001f
#define ONE_MB   0.999f      // 1 - BETA
#define EPS_NORM 1e-12f

#define SLOTS    64          // per-row edge bin (Poisson(16): P(>64) ~ 1e-20)

#define BK        64                 // K elements per smem pass
#define AS_STRIDE (BK + 8)           // 72 halves = 144B row stride

// ---------------- device scratch (no allocations allowed) ----------------
__device__ __half g_support[(size_t)MAXN * DIM];  // 25.6 MB, keep L2-resident
__device__ __half g_wt[DIM * DIM];                // W^T, [n][k] fp16
__device__ int    g_count[MAXN];
__device__ int2   g_slot [(size_t)MAXN * SLOTS];  // binned (col, val-bits)

// ---------------- PTX helpers ---------------------------------------------
__device__ __forceinline__ uint32_t smem_u32(const void* p) {
    return (uint32_t)__cvta_generic_to_shared(p);
}
__device__ __forceinline__ void ldm_x4(uint32_t& r0, uint32_t& r1,
                                       uint32_t& r2, uint32_t& r3, uint32_t addr) {
    asm volatile("ldmatrix.sync.aligned.m8n8.x4.shared.b16 {%0,%1,%2,%3}, [%4];"
        : "=r"(r0), "=r"(r1), "=r"(r2), "=r"(r3) : "r"(addr));
}
__device__ __forceinline__ void mma16816(float* c, const uint32_t* a, const uint32_t* b) {
    asm volatile("mma.sync.aligned.m16n8k16.row.col.f32.f16.f16.f32 "
        "{%0,%1,%2,%3}, {%4,%5,%6,%7}, {%8,%9}, {%0,%1,%2,%3};"
        : "+f"(c[0]), "+f"(c[1]), "+f"(c[2]), "+f"(c[3])
        : "r"(a[0]), "r"(a[1]), "r"(a[2]), "r"(a[3]), "r"(b[0]), "r"(b[1]));
}

// ---------------- 0b. W [k][n] fp32 -> g_wt [n][k] fp16 -------------------
__global__ void wt_kernel(const float* __restrict__ W) {
    int tid = blockIdx.x * blockDim.x + threadIdx.x;
    if (tid < DIM * DIM) {
        int n = tid >> 7, k = tid & 127;
        g_wt[n * DIM + k] = __float2half_rn(W[k * DIM + n]);
    }
}

// ---------------- 1. support = input @ W  (HMMA fp16, fp32 accum) --------
__global__ __launch_bounds__(256) void gemm_hmma_kernel(
    const float* __restrict__ A, int M)
{
    __shared__ __half As[128 * AS_STRIDE];   // [m][k_local]
    __shared__ __half Ws[128 * AS_STRIDE];   // [n][k_local]

    const int tid  = threadIdx.x;
    const int warp = tid >> 5;
    const int lane = tid & 31;
    const int m0   = blockIdx.x * 128;

    const int wm = warp & 1;
    const int wn = warp >> 1;
    const int mbase = wm * 64;
    const int nbase = wn * 32;

    float acc[4][4][4];
#pragma unroll
    for (int i = 0; i < 4; i++)
#pragma unroll
        for (int j = 0; j < 4; j++)
#pragma unroll
            for (int q = 0; q < 4; q++) acc[i][j][q] = 0.f;

    const float4* A4 = (const float4*)A;
    const uint32_t as_base = smem_u32(As);
    const uint32_t ws_base = smem_u32(Ws);

    const int mat = lane >> 3;
    const int rin = lane & 7;
    const int rofs = rin + (mat & 1) * 8;
    const int kofs = (mat >> 1) * 8;

    for (int pass = 0; pass < 2; pass++) {
        const int kg = pass * BK;

#pragma unroll
        for (int it = 0; it < 8; it++) {
            int idx4 = tid + it * 256;
            int row  = idx4 >> 4;
            int c4   = idx4 & 15;
            int rg   = m0 + row; if (rg >= M) rg = M - 1;
            float4 f = __ldcs(&A4[(size_t)rg * DIM4 + (kg >> 2) + c4]);  // stream A
            __half2* dst = (__half2*)&As[row * AS_STRIDE + c4 * 4];
            dst[0] = __floats2half2_rn(f.x, f.y);
            dst[1] = __floats2half2_rn(f.z, f.w);
        }
#pragma unroll
        for (int it = 0; it < 4; it++) {
            int idx8 = tid + it * 256;
            int row  = idx8 >> 3;
            int c8   = idx8 & 7;
            uint4 u = *(const uint4*)&g_wt[row * DIM + kg + c8 * 8];
            *(uint4*)&Ws[row * AS_STRIDE + c8 * 8] = u;
        }
        __syncthreads();

#pragma unroll
        for (int ks = 0; ks < BK / 16; ks++) {
            const int k0 = ks * 16;

            uint32_t a[4][4];
#pragma unroll
            for (int mt = 0; mt < 4; mt++) {
                uint32_t addr = as_base +
                    ((mbase + mt * 16 + rofs) * AS_STRIDE + k0 + kofs) * 2;
                ldm_x4(a[mt][0], a[mt][1], a[mt][2], a[mt][3], addr);
            }
            uint32_t b[4][2];
#pragma unroll
            for (int g = 0; g < 2; g++) {
                uint32_t addr = ws_base +
                    ((nbase + g * 16 + rofs) * AS_STRIDE + k0 + kofs) * 2;
                uint32_t r0, r1, r2, r3;
                ldm_x4(r0, r1, r2, r3, addr);
                b[g * 2 + 0][0] = r0; b[g * 2 + 0][1] = r2;
                b[g * 2 + 1][0] = r1; b[g * 2 + 1][1] = r3;
            }
#pragma unroll
            for (int mt = 0; mt < 4; mt++)
#pragma unroll
                for (int nt = 0; nt < 4; nt++)
                    mma16816(acc[mt][nt], a[mt], b[nt]);
        }
        __syncthreads();
    }

    // support stores: default caching (we WANT these resident in L2)
#pragma unroll
    for (int mt = 0; mt < 4; mt++) {
        int m1 = m0 + mbase + mt * 16 + (lane >> 2);
        int m2 = m1 + 8;
#pragma unroll
        for (int nt = 0; nt < 4; nt++) {
            int nc = nbase + nt * 8 + (lane & 3) * 2;
            if (m1 < M)
                *(__half2*)&g_support[(size_t)m1 * DIM + nc] =
                    __floats2half2_rn(acc[mt][nt][0], acc[mt][nt][1]);
            if (m2 < M)
                *(__half2*)&g_support[(size_t)m2 * DIM + nc] =
                    __floats2half2_rn(acc[mt][nt][2], acc[mt][nt][3]);
        }
    }
}

// ---------------- 2. single-pass slot scatter (1 edge/thread: max MLP) -----
__global__ void slot_scatter_kernel(const int* __restrict__ rows,
                                    const int* __restrict__ cols,
                                    const float* __restrict__ vals, int e) {
    int i = blockIdx.x * blockDim.x + threadIdx.x;
    if (i < e) {
        int   r = __ldcs(rows + i);
        int   c = __ldcs(cols + i);
        float v = __ldcs(vals + i);
        int pos = atomicAdd(&g_count[r], 1);
        g_slot[(size_t)r * SLOTS + pos] = make_int2(c, __float_as_int(v));
    }
}

// ---------------- 3. fused gather + blend + L2-normalize + bias ----------
// One warp per row; lane owns 4 cols (8B fp16). Lane-strided edge preload +
// shfl broadcast (R11 structure), x4-unrolled independent gathers.
__global__ __launch_bounds__(256) void agg_kernel(
    const float* __restrict__ input,
    const float* __restrict__ bias,
    float* __restrict__ out, int n)
{
    const int gtid = blockIdx.x * blockDim.x + threadIdx.x;
    const int row  = gtid >> 5;
    const int lane = gtid & 31;
    if (row >= n) return;

    const int cnt = min(g_count[row], SLOTS);
    const int2* slot = g_slot + (size_t)row * SLOTS;

    // lane-fixed byte base into support; per-edge offset = col * 256B
    const char* supb = (const char*)g_support + lane * 8;

    float4 acc = make_float4(0.f, 0.f, 0.f, 0.f);

    for (int e0 = 0; e0 < cnt; e0 += 32) {
        int  e = e0 + lane;
        int2 ed = (e < cnt) ? __ldcs(&slot[e]) : make_int2(0, 0);
        int m = min(32, cnt - e0);

        int j = 0;
        for (; j + 4 <= m; j += 4) {
            int   c0 = __shfl_sync(0xffffffffu, ed.x, j + 0);
            int   c1 = __shfl_sync(0xffffffffu, ed.x, j + 1);
            int   c2 = __shfl_sync(0xffffffffu, ed.x, j + 2);
            int   c3 = __shfl_sync(0xffffffffu, ed.x, j + 3);
            float v0 = __int_as_float(__shfl_sync(0xffffffffu, ed.y, j + 0));
            float v1 = __int_as_float(__shfl_sync(0xffffffffu, ed.y, j + 1));
            float v2 = __int_as_float(__shfl_sync(0xffffffffu, ed.y, j + 2));
            float v3 = __int_as_float(__shfl_sync(0xffffffffu, ed.y, j + 3));
            uint2 u0 = *(const uint2*)(supb + ((size_t)(unsigned)c0 << 8));
            uint2 u1 = *(const uint2*)(supb + ((size_t)(unsigned)c1 << 8));
            uint2 u2 = *(const uint2*)(supb + ((size_t)(unsigned)c2 << 8));
            uint2 u3 = *(const uint2*)(supb + ((size_t)(unsigned)c3 << 8));

            float2 a0 = __half22float2(*(__half2*)&u0.x);
            float2 b0 = __half22float2(*(__half2*)&u0.y);
            acc.x = fmaf(v0, a0.x, acc.x); acc.y = fmaf(v0, a0.y, acc.y);
            acc.z = fmaf(v0, b0.x, acc.z); acc.w = fmaf(v0, b0.y, acc.w);
            float2 a1 = __half22float2(*(__half2*)&u1.x);
            float2 b1 = __half22float2(*(__half2*)&u1.y);
            acc.x = fmaf(v1, a1.x, acc.x); acc.y = fmaf(v1, a1.y, acc.y);
            acc.z = fmaf(v1, b1.x, acc.z); acc.w = fmaf(v1, b1.y, acc.w);
            float2 a2 = __half22float2(*(__half2*)&u2.x);
            float2 b2 = __half22float2(*(__half2*)&u2.y);
            acc.x = fmaf(v2, a2.x, acc.x); acc.y = fmaf(v2, a2.y, acc.y);
            acc.z = fmaf(v2, b2.x, acc.z); acc.w = fmaf(v2, b2.y, acc.w);
            float2 a3 = __half22float2(*(__half2*)&u3.x);
            float2 b3 = __half22float2(*(__half2*)&u3.y);
            acc.x = fmaf(v3, a3.x, acc.x); acc.y = fmaf(v3, a3.y, acc.y);
            acc.z = fmaf(v3, b3.x, acc.z); acc.w = fmaf(v3, b3.y, acc.w);
        }
        for (; j < m; j++) {
            int   cj = __shfl_sync(0xffffffffu, ed.x, j);
            float vj = __int_as_float(__shfl_sync(0xffffffffu, ed.y, j));
            uint2 u  = *(const uint2*)(supb + ((size_t)(unsigned)cj << 8));
            float2 s0 = __half22float2(*(__half2*)&u.x);
            float2 s1 = __half22float2(*(__half2*)&u.y);
            acc.x = fmaf(vj, s0.x, acc.x);
            acc.y = fmaf(vj, s0.y, acc.y);
            acc.z = fmaf(vj, s1.x, acc.z);
            acc.w = fmaf(vj, s1.y, acc.w);
        }
    }

    float4 in4 = __ldcs(&((const float4*)input)[row * DIM4 + lane]);  // stream
    float4 o;
    o.x = fmaf(BETA, in4.x, ONE_MB * acc.x);
    o.y = fmaf(BETA, in4.y, ONE_MB * acc.y);
    o.z = fmaf(BETA, in4.z, ONE_MB * acc.z);
    o.w = fmaf(BETA, in4.w, ONE_MB * acc.w);

    float ss = o.x * o.x + o.y * o.y + o.z * o.z + o.w * o.w;
#pragma unroll
    for (int off = 16; off; off >>= 1)
        ss += __shfl_xor_sync(0xffffffffu, ss, off);

    float inv = 1.f / fmaxf(sqrtf(ss), EPS_NORM);

    float4 b4 = ((const float4*)bias)[lane];
    o.x = fmaf(o.x, inv, b4.x);
    o.y = fmaf(o.y, inv, b4.y);
    o.z = fmaf(o.z, inv, b4.z);
    o.w = fmaf(o.w, inv, b4.w);

    __stcs(&((float4*)out)[row * DIM4 + lane], o);     // streaming store
}

// ---------------- launch ---------------------------------------------------
extern "C" void kernel_launch(void* const* d_in, const int* in_sizes, int n_in,
                              void* d_out, int out_size) {
    const float* input     = (const float*)d_in[0];
    const int*   edge_rows = (const int*)  d_in[1];
    const int*   edge_cols = (const int*)  d_in[2];
    const float* edge_vals = (const float*)d_in[3];
    const float* weight    = (const float*)d_in[4];
    const float* bias      = (const float*)d_in[5];
    float*       out       = (float*)d_out;

    const int n = in_sizes[0] / DIM;   // 100000
    const int e = in_sizes[1];         // 1600000

    static cudaStream_t s2 = nullptr;
    static cudaEvent_t  ev_fork = nullptr, ev_join = nullptr;
    static int* count_addr = nullptr;
    if (!s2) {
        cudaStreamCreateWithFlags(&s2, cudaStreamNonBlocking);
        cudaEventCreateWithFlags(&ev_fork, cudaEventDisableTiming);
        cudaEventCreateWithFlags(&ev_join, cudaEventDisableTiming);
        cudaGetSymbolAddress((void**)&count_addr, g_count);
    }

    // fork
    cudaEventRecord(ev_fork, 0);
    cudaStreamWaitEvent(s2, ev_fork, 0);

    // branch B (side stream): dense projection
    wt_kernel<<<(DIM * DIM + 255) / 256, 256, 0, s2>>>(weight);
    gemm_hmma_kernel<<<(n + 127) / 128, 256, 0, s2>>>(input, n);
    cudaEventRecord(ev_join, s2);

    // branch A (main stream): zero counters (memset node) + edge binning
    cudaMemsetAsync(count_addr, 0, (size_t)n * sizeof(int), 0);
    slot_scatter_kernel<<<(e + 255) / 256, 256>>>(edge_rows, edge_cols, edge_vals, e);

    // join: agg needs both support (branch B) and bins (branch A)
    cudaStreamWaitEvent(0, ev_join, 0);
    agg_kernel<<<((long long)n * 32 + 255) / 256, 256>>>(input, bias, out, n);
}